// round 1
// baseline (speedup 1.0000x reference)
#include <cuda_runtime.h>
#include <math.h>

// Problem constants (fixed by the reference)
#define NB 4
#define LQ 5440
#define LV 5440
#define CD 256
#define NH 8
#define HD 32
#define MROWS (NB * LQ)   // 21760

// Scratch (device globals: no allocation allowed in kernel_launch)
__device__ float g_vproj[(size_t)MROWS * CD];   // value @ W_val + b_val, [B*Lv, 256]
__device__ float g_off  [(size_t)MROWS * CD];   // query @ W_off + b_off, [B*Lq, 256]
__device__ float g_attn [(size_t)MROWS * 128];  // query @ W_attn + b_attn, [B*Lq, 128]
__device__ float g_acc  [(size_t)MROWS * CD];   // sampled accumulator, [B*Lq, 256]

// ---------------------------------------------------------------------------
// Simple register-tiled fp32 GEMM: C[M,N] = A[M,K=256] @ B[256,N] + bias[N]
// BM=BN=64, BK=16, 256 threads, 4x4 per thread. M divisible by 64, N by 64.
// ---------------------------------------------------------------------------
template <int N>
__global__ __launch_bounds__(256) void gemm_bias_k256(
    const float* __restrict__ A, const float* __restrict__ B,
    const float* __restrict__ bias, float* __restrict__ C)
{
    constexpr int K = 256;
    __shared__ float As[16][64];   // [k][m] (A tile transposed)
    __shared__ float Bs[16][64];   // [k][n]

    const int tid = threadIdx.x;
    const int br = blockIdx.y;     // M tile
    const int bc = blockIdx.x;     // N tile

    const int aRow = tid >> 2;          // 0..63
    const int aCol = (tid & 3) * 4;     // 0,4,8,12
    const int bRow = tid >> 4;          // 0..15
    const int bCol = (tid & 15) * 4;    // 0..60

    const int tr = (tid >> 4) * 4;      // output row offset in tile
    const int tc = (tid & 15) * 4;      // output col offset in tile

    float acc[4][4] = {};

    const float* Aptr = A + (size_t)(br * 64 + aRow) * K + aCol;
    const float* Bptr = B + (size_t)bRow * N + bc * 64 + bCol;

    for (int k0 = 0; k0 < K; k0 += 16) {
        float4 av = *(const float4*)(Aptr + k0);
        As[aCol + 0][aRow] = av.x;
        As[aCol + 1][aRow] = av.y;
        As[aCol + 2][aRow] = av.z;
        As[aCol + 3][aRow] = av.w;
        *(float4*)&Bs[bRow][bCol] = *(const float4*)(Bptr + (size_t)k0 * N);
        __syncthreads();

#pragma unroll
        for (int kk = 0; kk < 16; kk++) {
            float ar[4], bb[4];
#pragma unroll
            for (int i = 0; i < 4; i++) ar[i] = As[kk][tr + i];
#pragma unroll
            for (int j = 0; j < 4; j++) bb[j] = Bs[kk][tc + j];
#pragma unroll
            for (int i = 0; i < 4; i++)
#pragma unroll
                for (int j = 0; j < 4; j++)
                    acc[i][j] = fmaf(ar[i], bb[j], acc[i][j]);
        }
        __syncthreads();
    }

    float4 bv = *(const float4*)&bias[bc * 64 + tc];
#pragma unroll
    for (int i = 0; i < 4; i++) {
        const int row = br * 64 + tr + i;
        float4 o;
        o.x = acc[i][0] + bv.x;
        o.y = acc[i][1] + bv.y;
        o.z = acc[i][2] + bv.z;
        o.w = acc[i][3] + bv.w;
        *(float4*)&C[(size_t)row * N + bc * 64 + tc] = o;
    }
}

// ---------------------------------------------------------------------------
// Deformable sampling: one block per (b, q). Warp h handles head h, lane = d.
// Every bilinear tap is a coalesced 128B warp load from g_vproj.
// ---------------------------------------------------------------------------
__global__ __launch_bounds__(256) void ms_sample_kernel(
    const float* __restrict__ refp)  // [B, Lq, 4, 2]
{
    const int bq = blockIdx.x;           // b*LQ + q
    const int t  = threadIdx.x;          // 0..255
    const int h  = t >> 5;               // head (warp)
    const int lid = t & 31;              // lane = head_dim index

    __shared__ float s_coord[256];       // [h][lp][xy] unnormalized pixel coords
    __shared__ float s_w[NH][16];        // softmax weights

    // --- sampling locations: u = ref*dim + off - 0.5  (offset_norm == grid dim)
    {
        const int l = (t >> 3) & 3;
        const float dim = (float)(64 >> l);
        const int xy = t & 1;
        const float ref = refp[((size_t)bq * 4 + l) * 2 + xy];
        const float off = g_off[(size_t)bq * 256 + t];
        s_coord[t] = fmaf(ref, dim, off) - 0.5f;
    }

    // --- softmax over 16 (level,point) logits per head, via warp shuffles
    {
        const float* ap = g_attn + (size_t)bq * 128 + h * 16;
        float logit = (lid < 16) ? ap[lid] : -1e30f;
        float m = logit;
#pragma unroll
        for (int o = 16; o; o >>= 1) m = fmaxf(m, __shfl_xor_sync(0xFFFFFFFFu, m, o));
        float e = (lid < 16) ? __expf(logit - m) : 0.0f;
        float s = e;
#pragma unroll
        for (int o = 16; o; o >>= 1) s += __shfl_xor_sync(0xFFFFFFFFu, s, o);
        if (lid < 16) s_w[h][lid] = e / s;
    }
    __syncthreads();

    const int b = bq / LQ;
    const float* vbase = g_vproj + (size_t)b * LV * CD + h * HD + lid;

    float acc = 0.0f;
#pragma unroll
    for (int lp = 0; lp < 16; lp++) {
        const int l = lp >> 2;
        const int W = 64 >> l;                                    // square levels
        const int start = (l == 0) ? 0 : (l == 1) ? 4096 : (l == 2) ? 5120 : 5376;

        const float x = s_coord[h * 32 + lp * 2 + 0];
        const float y = s_coord[h * 32 + lp * 2 + 1];
        const float w = s_w[h][lp];

        const float x0f = floorf(x), y0f = floorf(y);
        const int x0 = (int)x0f, y0 = (int)y0f;
        const float wx = x - x0f, wy = y - y0f;

        const bool xin0 = (x0 >= 0) & (x0 < W);
        const bool xin1 = (x0 + 1 >= 0) & (x0 + 1 < W);
        const bool yin0 = (y0 >= 0) & (y0 < W);
        const bool yin1 = (y0 + 1 >= 0) & (y0 + 1 < W);

        float v00 = 0.f, v10 = 0.f, v01 = 0.f, v11 = 0.f;
        if (yin0) {
            const int rb = start + y0 * W;
            if (xin0) v00 = vbase[(size_t)(rb + x0) * CD];
            if (xin1) v10 = vbase[(size_t)(rb + x0 + 1) * CD];
        }
        if (yin1) {
            const int rb = start + (y0 + 1) * W;
            if (xin0) v01 = vbase[(size_t)(rb + x0) * CD];
            if (xin1) v11 = vbase[(size_t)(rb + x0 + 1) * CD];
        }
        const float sample = (v00 * (1.f - wx) + v10 * wx) * (1.f - wy)
                           + (v01 * (1.f - wx) + v11 * wx) * wy;
        acc = fmaf(w, sample, acc);
    }

    g_acc[(size_t)bq * 256 + t] = acc;   // layout [B, Lq, h*HD + d] == [B, Lq, C]
}

// ---------------------------------------------------------------------------
// kernel_launch
// Inputs (metadata order): query, reference_points, value, W_off, b_off,
//                          W_attn, b_attn, W_val, b_val, W_out, b_out
// ---------------------------------------------------------------------------
extern "C" void kernel_launch(void* const* d_in, const int* in_sizes, int n_in,
                              void* d_out, int out_size)
{
    const float* query = (const float*)d_in[0];
    const float* refp  = (const float*)d_in[1];
    const float* value = (const float*)d_in[2];
    const float* W_off = (const float*)d_in[3];
    const float* b_off = (const float*)d_in[4];
    const float* W_at  = (const float*)d_in[5];
    const float* b_at  = (const float*)d_in[6];
    const float* W_val = (const float*)d_in[7];
    const float* b_val = (const float*)d_in[8];
    const float* W_out = (const float*)d_in[9];
    const float* b_out = (const float*)d_in[10];
    float* out = (float*)d_out;

    float *vproj, *offs, *attn, *accb;
    cudaGetSymbolAddress((void**)&vproj, g_vproj);
    cudaGetSymbolAddress((void**)&offs,  g_off);
    cudaGetSymbolAddress((void**)&attn,  g_attn);
    cudaGetSymbolAddress((void**)&accb,  g_acc);

    dim3 blk(256);
    dim3 g256(CD / 64, MROWS / 64);   // (4, 340)
    dim3 g128(128 / 64, MROWS / 64);  // (2, 340)

    // 1. value projection
    gemm_bias_k256<256><<<g256, blk>>>(value, W_val, b_val, vproj);
    // 2. offset projection
    gemm_bias_k256<256><<<g256, blk>>>(query, W_off, b_off, offs);
    // 3. attention-logit projection
    gemm_bias_k256<128><<<g128, blk>>>(query, W_at, b_at, attn);
    // 4. softmax + multi-scale deformable bilinear sampling
    ms_sample_kernel<<<MROWS, blk>>>(refp);
    // 5. output projection -> d_out
    gemm_bias_k256<256><<<g256, blk>>>(accb, W_out, b_out, out);
}

// round 2
// speedup vs baseline: 1.9708x; 1.9708x over previous
#include <cuda_runtime.h>
#include <math.h>

// Problem constants (fixed by the reference)
#define NB 4
#define LQ 5440
#define LV 5440
#define CD 256
#define NH 8
#define HD 32
#define MROWS (NB * LQ)   // 21760

// Scratch (device globals: no allocation allowed in kernel_launch)
__device__ float g_vproj[(size_t)MROWS * CD];   // value @ W_val + b_val
__device__ float g_off  [(size_t)MROWS * CD];   // query @ W_off + b_off
__device__ float g_attn [(size_t)MROWS * 128];  // query @ W_attn + b_attn
__device__ float g_acc  [(size_t)MROWS * CD];   // sampled accumulator

// ---------------------------------------------------------------------------
// tf32 tensor-core GEMM: C[M, N] = A[M, 256] @ B[256, N] + bias[N]
// Block tile 128x128 (BK=16, double-buffered), 8 warps of 64x32,
// mma.sync.aligned.m16n8k8.row.col.f32.tf32.tf32.f32
// ---------------------------------------------------------------------------
__device__ __forceinline__ unsigned f2tf(float f) {
    unsigned r;
    asm("cvt.rna.tf32.f32 %0, %1;" : "=r"(r) : "f"(f));
    return r;
}

__device__ __forceinline__ void mma_tf32(float* c, const unsigned* a, const unsigned* b) {
    asm volatile(
        "mma.sync.aligned.m16n8k8.row.col.f32.tf32.tf32.f32 "
        "{%0,%1,%2,%3}, {%4,%5,%6,%7}, {%8,%9}, {%0,%1,%2,%3};"
        : "+f"(c[0]), "+f"(c[1]), "+f"(c[2]), "+f"(c[3])
        : "r"(a[0]), "r"(a[1]), "r"(a[2]), "r"(a[3]), "r"(b[0]), "r"(b[1]));
}

template <int N>
__global__ __launch_bounds__(256) void gemm_tf32(
    const float* __restrict__ A, const float* __restrict__ B,
    const float* __restrict__ bias, float* __restrict__ C)
{
    constexpr int K = 256;
    __shared__ __align__(16) float As[2][128][20];   // [m][k], stride 20: conflict-free frag loads
    __shared__ __align__(16) float Bs[2][16][136];   // [k][n], stride 136: conflict-free frag loads

    const int tid  = threadIdx.x;
    const int lane = tid & 31;
    const int warp = tid >> 5;
    const int br   = blockIdx.y;           // M tile
    const int bc   = blockIdx.x;           // N tile
    const int wm   = (warp >> 2) * 64;     // warp M offset in tile
    const int wn   = (warp & 3) * 32;      // warp N offset in tile

    // global->smem mapping (each thread: 2 float4 of A, 2 float4 of B per stage)
    const int arow0 = tid >> 2;            // 0..63 (+64 for i=1)
    const int aq0   = (tid & 3) * 4;       // k quad within 16
    const int brow0 = tid >> 5;            // 0..7 (+8 for i=1)
    const int bq0   = (tid & 31) * 4;      // n within 128

    const float* Abase = A + (size_t)(br * 128) * K;
    const float* Bbase = B + bc * 128;

    float4 la[2], lb[2];
    float acc[4][4][4] = {};

    // prologue: stage 0
    {
        const int k0 = 0;
#pragma unroll
        for (int i = 0; i < 2; i++) {
            la[i] = *(const float4*)(Abase + (size_t)(arow0 + i * 64) * K + k0 + aq0);
            lb[i] = *(const float4*)(Bbase + (size_t)(k0 + brow0 + i * 8) * N + bq0);
        }
#pragma unroll
        for (int i = 0; i < 2; i++) {
            *(float4*)&As[0][arow0 + i * 64][aq0] = la[i];
            *(float4*)&Bs[0][brow0 + i * 8][bq0]  = lb[i];
        }
    }
    __syncthreads();

#pragma unroll 1
    for (int s = 0; s < K / 16; s++) {
        const int buf = s & 1;
        if (s + 1 < K / 16) {
            const int k0 = (s + 1) * 16;
#pragma unroll
            for (int i = 0; i < 2; i++) {
                la[i] = *(const float4*)(Abase + (size_t)(arow0 + i * 64) * K + k0 + aq0);
                lb[i] = *(const float4*)(Bbase + (size_t)(k0 + brow0 + i * 8) * N + bq0);
            }
        }

        // compute on buf
#pragma unroll
        for (int kk = 0; kk < 16; kk += 8) {
            unsigned af[4][4], bf[4][2];
            const int kc = kk + (lane & 3);
#pragma unroll
            for (int mi = 0; mi < 4; mi++) {
                const int row = wm + mi * 16 + (lane >> 2);
                af[mi][0] = f2tf(As[buf][row][kc]);
                af[mi][1] = f2tf(As[buf][row + 8][kc]);
                af[mi][2] = f2tf(As[buf][row][kc + 4]);
                af[mi][3] = f2tf(As[buf][row + 8][kc + 4]);
            }
#pragma unroll
            for (int ni = 0; ni < 4; ni++) {
                const int col = wn + ni * 8 + (lane >> 2);
                bf[ni][0] = f2tf(Bs[buf][kc][col]);
                bf[ni][1] = f2tf(Bs[buf][kc + 4][col]);
            }
#pragma unroll
            for (int mi = 0; mi < 4; mi++)
#pragma unroll
                for (int ni = 0; ni < 4; ni++)
                    mma_tf32(acc[mi][ni], af[mi], bf[ni]);
        }

        if (s + 1 < K / 16) {
            const int nb = (s + 1) & 1;
#pragma unroll
            for (int i = 0; i < 2; i++) {
                *(float4*)&As[nb][arow0 + i * 64][aq0] = la[i];
                *(float4*)&Bs[nb][brow0 + i * 8][bq0]  = lb[i];
            }
            __syncthreads();
        }
    }

    // epilogue: bias add + store (float2, cols are even)
#pragma unroll
    for (int mi = 0; mi < 4; mi++) {
        const int r = br * 128 + wm + mi * 16 + (lane >> 2);
#pragma unroll
        for (int ni = 0; ni < 4; ni++) {
            const int c = bc * 128 + wn + ni * 8 + (lane & 3) * 2;
            const float2 bv = *(const float2*)&bias[c];
            float2 o0, o1;
            o0.x = acc[mi][ni][0] + bv.x;
            o0.y = acc[mi][ni][1] + bv.y;
            o1.x = acc[mi][ni][2] + bv.x;
            o1.y = acc[mi][ni][3] + bv.y;
            *(float2*)&C[(size_t)r * N + c]       = o0;
            *(float2*)&C[(size_t)(r + 8) * N + c] = o1;
        }
    }
}

// ---------------------------------------------------------------------------
// Deformable sampling. One block per (q, b). Phase 1: per-head softmax (warps).
// Phase 2: threads 0-127 precompute 4 tap (index, weight) pairs for one
// (head, level, point) each into smem. Phase 3: warp h gathers 64 taps for
// head h with broadcast LDS.64 + coalesced 128B LDG per tap.
// ---------------------------------------------------------------------------
__global__ __launch_bounds__(256) void ms_sample_kernel(
    const float* __restrict__ refp)   // [B, Lq, 4, 2]
{
    const int q  = blockIdx.x;
    const int b  = blockIdx.y;
    const int bq = b * LQ + q;
    const int t  = threadIdx.x;
    const int h  = t >> 5;
    const int lid = t & 31;

    __shared__ float s_aw[NH][16];
    __shared__ int2  s_tap[NH * 64];   // {value-row idx, weight bits}

    // --- softmax over 16 logits per head (warp h, lanes 0-15)
    {
        const float* ap = g_attn + (size_t)bq * 128 + h * 16;
        float logit = (lid < 16) ? ap[lid] : -1e30f;
        float m = logit;
#pragma unroll
        for (int o = 16; o; o >>= 1) m = fmaxf(m, __shfl_xor_sync(0xFFFFFFFFu, m, o));
        float e = (lid < 16) ? __expf(logit - m) : 0.0f;
        float ssum = e;
#pragma unroll
        for (int o = 16; o; o >>= 1) ssum += __shfl_xor_sync(0xFFFFFFFFu, ssum, o);
        if (lid < 16) s_aw[h][lid] = e / ssum;
    }
    __syncthreads();

    // --- tap precompute: thread t<128 handles (head hh, levelpoint lp)
    if (t < 128) {
        const int hh = t >> 4;
        const int lp = t & 15;
        const int l  = lp >> 2;
        const int W  = 64 >> l;
        const int start = (l == 0) ? 0 : (l == 1) ? 4096 : (l == 2) ? 5120 : 5376;

        const float aw = s_aw[hh][lp];
        const float rx = refp[((size_t)bq * 4 + l) * 2 + 0];
        const float ry = refp[((size_t)bq * 4 + l) * 2 + 1];
        const float* op = g_off + (size_t)bq * 256 + hh * 32 + lp * 2;

        const float x = fmaf(rx, (float)W, op[0]) - 0.5f;
        const float y = fmaf(ry, (float)W, op[1]) - 0.5f;
        const float x0f = floorf(x), y0f = floorf(y);
        const int x0 = (int)x0f, y0 = (int)y0f;
        const float wx = x - x0f, wy = y - y0f;

        const bool xi0 = (x0 >= 0) && (x0 < W);
        const bool xi1 = (x0 + 1 >= 0) && (x0 + 1 < W);
        const bool yi0 = (y0 >= 0) && (y0 < W);
        const bool yi1 = (y0 + 1 >= 0) && (y0 + 1 < W);

        const int i00 = start + y0 * W + x0;
        int2* tp = &s_tap[hh * 64 + lp * 4];
        bool v;
        v = xi0 && yi0;
        tp[0] = make_int2(v ? i00 : 0,         __float_as_int(v ? aw * (1.f - wx) * (1.f - wy) : 0.f));
        v = xi1 && yi0;
        tp[1] = make_int2(v ? i00 + 1 : 0,     __float_as_int(v ? aw * wx * (1.f - wy) : 0.f));
        v = xi0 && yi1;
        tp[2] = make_int2(v ? i00 + W : 0,     __float_as_int(v ? aw * (1.f - wx) * wy : 0.f));
        v = xi1 && yi1;
        tp[3] = make_int2(v ? i00 + W + 1 : 0, __float_as_int(v ? aw * wx * wy : 0.f));
    }
    __syncthreads();

    // --- gather: warp h, lane = head_dim channel
    const float* vbase = g_vproj + (size_t)b * LV * CD + h * HD + lid;
    const int2* taps = &s_tap[h * 64];

    float acc = 0.0f;
#pragma unroll
    for (int j = 0; j < 64; j++) {
        const int2 tv = taps[j];
        const float w = __int_as_float(tv.y);
        if (w != 0.0f)
            acc = fmaf(w, __ldg(vbase + (size_t)tv.x * CD), acc);
    }

    g_acc[(size_t)bq * 256 + t] = acc;
}

// ---------------------------------------------------------------------------
// kernel_launch
// Inputs: query, reference_points, value, W_off, b_off, W_attn, b_attn,
//         W_val, b_val, W_out, b_out
// ---------------------------------------------------------------------------
extern "C" void kernel_launch(void* const* d_in, const int* in_sizes, int n_in,
                              void* d_out, int out_size)
{
    const float* query = (const float*)d_in[0];
    const float* refp  = (const float*)d_in[1];
    const float* value = (const float*)d_in[2];
    const float* W_off = (const float*)d_in[3];
    const float* b_off = (const float*)d_in[4];
    const float* W_at  = (const float*)d_in[5];
    const float* b_at  = (const float*)d_in[6];
    const float* W_val = (const float*)d_in[7];
    const float* b_val = (const float*)d_in[8];
    const float* W_out = (const float*)d_in[9];
    const float* b_out = (const float*)d_in[10];
    float* out = (float*)d_out;

    float *vproj, *offs, *attn, *accb;
    cudaGetSymbolAddress((void**)&vproj, g_vproj);
    cudaGetSymbolAddress((void**)&offs,  g_off);
    cudaGetSymbolAddress((void**)&attn,  g_attn);
    cudaGetSymbolAddress((void**)&accb,  g_acc);

    dim3 blk(256);
    dim3 g256(CD / 128, MROWS / 128);   // (2, 170)
    dim3 g128(1, MROWS / 128);          // (1, 170)

    gemm_tf32<256><<<g256, blk>>>(value, W_val, b_val, vproj);
    gemm_tf32<256><<<g256, blk>>>(query, W_off, b_off, offs);
    gemm_tf32<128><<<g128, blk>>>(query, W_at, b_at, attn);
    ms_sample_kernel<<<dim3(LQ, NB), blk>>>(refp);
    gemm_tf32<256><<<g256, blk>>>(accb, W_out, b_out, out);
}

// round 3
// speedup vs baseline: 2.1996x; 1.1161x over previous
#include <cuda_runtime.h>
#include <math.h>

// Problem constants (fixed by the reference)
#define NB 4
#define LQ 5440
#define LV 5440
#define CD 256
#define NH 8
#define HD 32
#define MROWS (NB * LQ)   // 21760
#define NFUSE 384         // fused off(256) + attn(128) projection width

// Scratch (device globals: no allocation allowed in kernel_launch)
__device__ float g_vproj  [(size_t)MROWS * CD];     // value @ W_val + b_val
__device__ float g_offattn[(size_t)MROWS * NFUSE];  // query @ [W_off|W_attn] + bias
__device__ float g_acc    [(size_t)MROWS * CD];     // sampled accumulator
__device__ float g_Wf     [256 * NFUSE];            // packed fused weights
__device__ float g_bf     [NFUSE];                  // packed fused bias

// ---------------------------------------------------------------------------
// Weight packing: Wf = [W_off | W_attn], bf = [b_off | b_attn]
// ---------------------------------------------------------------------------
__global__ void pack_weights(const float* __restrict__ W_off, const float* __restrict__ b_off,
                             const float* __restrict__ W_at,  const float* __restrict__ b_at)
{
    const int i = blockIdx.x * 256 + threadIdx.x;   // over 256*384
    const int k = i / NFUSE;
    const int n = i % NFUSE;
    g_Wf[i] = (n < 256) ? W_off[k * 256 + n] : W_at[k * 128 + (n - 256)];
    if (i < NFUSE) g_bf[i] = (i < 256) ? b_off[i] : b_at[i - 256];
}

// ---------------------------------------------------------------------------
// tf32 tensor-core GEMM: C[M, N] = A[M, 256] @ B[256, N] + bias[N]
// Block tile 128x128 (BK=16, double-buffered), 8 warps of 64x32.
// Operands converted to tf32 once at smem-store time.
// ---------------------------------------------------------------------------
__device__ __forceinline__ unsigned f2tf(float f) {
    unsigned r;
    asm("cvt.rna.tf32.f32 %0, %1;" : "=r"(r) : "f"(f));
    return r;
}

__device__ __forceinline__ void mma_tf32(float* c, const unsigned* a, const unsigned* b) {
    asm volatile(
        "mma.sync.aligned.m16n8k8.row.col.f32.tf32.tf32.f32 "
        "{%0,%1,%2,%3}, {%4,%5,%6,%7}, {%8,%9}, {%0,%1,%2,%3};"
        : "+f"(c[0]), "+f"(c[1]), "+f"(c[2]), "+f"(c[3])
        : "r"(a[0]), "r"(a[1]), "r"(a[2]), "r"(a[3]), "r"(b[0]), "r"(b[1]));
}

template <int N>
__global__ __launch_bounds__(256) void gemm_tf32(
    const float* __restrict__ A, const float* __restrict__ B,
    const float* __restrict__ bias, float* __restrict__ C)
{
    constexpr int K = 256;
    __shared__ __align__(16) unsigned As[2][128][20];   // [m][k] tf32 bits
    __shared__ __align__(16) unsigned Bs[2][16][136];   // [k][n] tf32 bits

    const int tid  = threadIdx.x;
    const int lane = tid & 31;
    const int warp = tid >> 5;
    const int br   = blockIdx.y;
    const int bc   = blockIdx.x;
    const int wm   = (warp >> 2) * 64;
    const int wn   = (warp & 3) * 32;

    const int arow0 = tid >> 2;            // 0..63 (+64)
    const int aq0   = (tid & 3) * 4;
    const int brow0 = tid >> 5;            // 0..7 (+8)
    const int bq0   = (tid & 31) * 4;

    const float* Abase = A + (size_t)(br * 128) * K;
    const float* Bbase = B + bc * 128;

    float4 la[2], lb[2];
    float acc[4][4][4] = {};

    auto stage_store = [&](int buf) {
#pragma unroll
        for (int i = 0; i < 2; i++) {
            unsigned* ap = &As[buf][arow0 + i * 64][aq0];
            ap[0] = f2tf(la[i].x); ap[1] = f2tf(la[i].y);
            ap[2] = f2tf(la[i].z); ap[3] = f2tf(la[i].w);
            unsigned* bp = &Bs[buf][brow0 + i * 8][bq0];
            bp[0] = f2tf(lb[i].x); bp[1] = f2tf(lb[i].y);
            bp[2] = f2tf(lb[i].z); bp[3] = f2tf(lb[i].w);
        }
    };

    // prologue
#pragma unroll
    for (int i = 0; i < 2; i++) {
        la[i] = *(const float4*)(Abase + (size_t)(arow0 + i * 64) * K + aq0);
        lb[i] = *(const float4*)(Bbase + (size_t)(brow0 + i * 8) * N + bq0);
    }
    stage_store(0);
    __syncthreads();

#pragma unroll 1
    for (int s = 0; s < K / 16; s++) {
        const int buf = s & 1;
        if (s + 1 < K / 16) {
            const int k0 = (s + 1) * 16;
#pragma unroll
            for (int i = 0; i < 2; i++) {
                la[i] = *(const float4*)(Abase + (size_t)(arow0 + i * 64) * K + k0 + aq0);
                lb[i] = *(const float4*)(Bbase + (size_t)(k0 + brow0 + i * 8) * N + bq0);
            }
        }

#pragma unroll
        for (int kk = 0; kk < 16; kk += 8) {
            unsigned af[4][4], bf[4][2];
            const int kc = kk + (lane & 3);
#pragma unroll
            for (int mi = 0; mi < 4; mi++) {
                const int row = wm + mi * 16 + (lane >> 2);
                af[mi][0] = As[buf][row][kc];
                af[mi][1] = As[buf][row + 8][kc];
                af[mi][2] = As[buf][row][kc + 4];
                af[mi][3] = As[buf][row + 8][kc + 4];
            }
#pragma unroll
            for (int ni = 0; ni < 4; ni++) {
                const int col = wn + ni * 8 + (lane >> 2);
                bf[ni][0] = Bs[buf][kc][col];
                bf[ni][1] = Bs[buf][kc + 4][col];
            }
#pragma unroll
            for (int mi = 0; mi < 4; mi++)
#pragma unroll
                for (int ni = 0; ni < 4; ni++)
                    mma_tf32(acc[mi][ni], af[mi], bf[ni]);
        }

        if (s + 1 < K / 16) {
            stage_store((s + 1) & 1);
            __syncthreads();
        }
    }

    // epilogue
#pragma unroll
    for (int mi = 0; mi < 4; mi++) {
        const int r = br * 128 + wm + mi * 16 + (lane >> 2);
#pragma unroll
        for (int ni = 0; ni < 4; ni++) {
            const int c = bc * 128 + wn + ni * 8 + (lane & 3) * 2;
            const float2 bv = *(const float2*)&bias[c];
            float2 o0, o1;
            o0.x = acc[mi][ni][0] + bv.x;
            o0.y = acc[mi][ni][1] + bv.y;
            o1.x = acc[mi][ni][2] + bv.x;
            o1.y = acc[mi][ni][3] + bv.y;
            *(float2*)&C[(size_t)r * N + c]       = o0;
            *(float2*)&C[(size_t)(r + 8) * N + c] = o1;
        }
    }
}

// ---------------------------------------------------------------------------
// Deformable sampling. Block = (q, b). Phase 1: per-head softmax.
// Phase 2: threads 0-127 each build 4 taps (idx, weight) for one (h, l, p).
// Phase 3: warp h gathers: 8 lanes per tap, LDG.128 per lane => 4 taps per
// load instruction; xor-shuffle reduction over lane strides 8/16.
// ---------------------------------------------------------------------------
__global__ __launch_bounds__(256) void ms_sample_kernel(
    const float* __restrict__ refp)   // [B, Lq, 4, 2]
{
    const int q  = blockIdx.x;
    const int b  = blockIdx.y;
    const int bq = b * LQ + q;
    const int t  = threadIdx.x;
    const int h  = t >> 5;
    const int lid = t & 31;

    __shared__ float s_aw[NH][16];
    __shared__ int2  s_tap[NH * 64];   // {value-row idx, weight bits}

    // --- softmax over 16 logits per head (warp h, lanes 0-15)
    {
        const float* ap = g_offattn + (size_t)bq * NFUSE + 256 + h * 16;
        float logit = (lid < 16) ? ap[lid] : -1e30f;
        float m = logit;
#pragma unroll
        for (int o = 16; o; o >>= 1) m = fmaxf(m, __shfl_xor_sync(0xFFFFFFFFu, m, o));
        float e = (lid < 16) ? __expf(logit - m) : 0.0f;
        float ssum = e;
#pragma unroll
        for (int o = 16; o; o >>= 1) ssum += __shfl_xor_sync(0xFFFFFFFFu, ssum, o);
        if (lid < 16) s_aw[h][lid] = e / ssum;
    }
    __syncthreads();

    // --- tap precompute: thread t<128 handles (head hh, levelpoint lp)
    if (t < 128) {
        const int hh = t >> 4;
        const int lp = t & 15;
        const int l  = lp >> 2;
        const int W  = 64 >> l;
        const int start = (l == 0) ? 0 : (l == 1) ? 4096 : (l == 2) ? 5120 : 5376;

        const float aw = s_aw[hh][lp];
        const float rx = refp[((size_t)bq * 4 + l) * 2 + 0];
        const float ry = refp[((size_t)bq * 4 + l) * 2 + 1];
        const float* op = g_offattn + (size_t)bq * NFUSE + hh * 32 + lp * 2;

        const float x = fmaf(rx, (float)W, op[0]) - 0.5f;
        const float y = fmaf(ry, (float)W, op[1]) - 0.5f;
        const float x0f = floorf(x), y0f = floorf(y);
        const int x0 = (int)x0f, y0 = (int)y0f;
        const float wx = x - x0f, wy = y - y0f;

        const bool xi0 = (x0 >= 0) && (x0 < W);
        const bool xi1 = (x0 + 1 >= 0) && (x0 + 1 < W);
        const bool yi0 = (y0 >= 0) && (y0 < W);
        const bool yi1 = (y0 + 1 >= 0) && (y0 + 1 < W);

        const int i00 = start + y0 * W + x0;
        int2* tp = &s_tap[hh * 64 + lp * 4];
        bool v;
        v = xi0 && yi0;
        tp[0] = make_int2(v ? i00 : 0,         __float_as_int(v ? aw * (1.f - wx) * (1.f - wy) : 0.f));
        v = xi1 && yi0;
        tp[1] = make_int2(v ? i00 + 1 : 0,     __float_as_int(v ? aw * wx * (1.f - wy) : 0.f));
        v = xi0 && yi1;
        tp[2] = make_int2(v ? i00 + W : 0,     __float_as_int(v ? aw * (1.f - wx) * wy : 0.f));
        v = xi1 && yi1;
        tp[3] = make_int2(v ? i00 + W + 1 : 0, __float_as_int(v ? aw * wx * wy : 0.f));
    }
    __syncthreads();

    // --- gather: warp h; 8 lanes per tap, float4 channels per lane
    const int sub = lid >> 3;         // tap sub-slot 0..3
    const int c4  = (lid & 7) * 4;    // channel quad
    const float* vb4 = g_vproj + (size_t)b * LV * CD + h * HD + c4;
    const int2* taps = &s_tap[h * 64];

    float ax = 0.f, ay = 0.f, az = 0.f, aw_ = 0.f;
#pragma unroll
    for (int j = 0; j < 16; j++) {
        const int2 tv = taps[j * 4 + sub];
        const float w = __int_as_float(tv.y);
        if (w != 0.0f) {
            const float4 v = *(const float4*)(vb4 + (size_t)tv.x * CD);
            ax = fmaf(w, v.x, ax);
            ay = fmaf(w, v.y, ay);
            az = fmaf(w, v.z, az);
            aw_ = fmaf(w, v.w, aw_);
        }
    }

    // reduce the 4 tap sub-slots (lanes l, l^8, l^16, l^24)
#pragma unroll
    for (int o = 8; o <= 16; o <<= 1) {
        ax  += __shfl_xor_sync(0xFFFFFFFFu, ax,  o);
        ay  += __shfl_xor_sync(0xFFFFFFFFu, ay,  o);
        az  += __shfl_xor_sync(0xFFFFFFFFu, az,  o);
        aw_ += __shfl_xor_sync(0xFFFFFFFFu, aw_, o);
    }

    if (lid < 8) {
        float4 o4 = make_float4(ax, ay, az, aw_);
        *(float4*)&g_acc[(size_t)bq * CD + h * HD + lid * 4] = o4;
    }
}

// ---------------------------------------------------------------------------
// kernel_launch
// Inputs: query, reference_points, value, W_off, b_off, W_attn, b_attn,
//         W_val, b_val, W_out, b_out
// ---------------------------------------------------------------------------
extern "C" void kernel_launch(void* const* d_in, const int* in_sizes, int n_in,
                              void* d_out, int out_size)
{
    const float* query = (const float*)d_in[0];
    const float* refp  = (const float*)d_in[1];
    const float* value = (const float*)d_in[2];
    const float* W_off = (const float*)d_in[3];
    const float* b_off = (const float*)d_in[4];
    const float* W_at  = (const float*)d_in[5];
    const float* b_at  = (const float*)d_in[6];
    const float* W_val = (const float*)d_in[7];
    const float* b_val = (const float*)d_in[8];
    const float* W_out = (const float*)d_in[9];
    const float* b_out = (const float*)d_in[10];
    float* out = (float*)d_out;

    float *vproj, *offattn, *accb, *wf, *bf;
    cudaGetSymbolAddress((void**)&vproj,   g_vproj);
    cudaGetSymbolAddress((void**)&offattn, g_offattn);
    cudaGetSymbolAddress((void**)&accb,    g_acc);
    cudaGetSymbolAddress((void**)&wf,      g_Wf);
    cudaGetSymbolAddress((void**)&bf,      g_bf);

    dim3 blk(256);
    dim3 g256(CD / 128, MROWS / 128);     // (2, 170)
    dim3 g384(NFUSE / 128, MROWS / 128);  // (3, 170)

    pack_weights<<<(256 * NFUSE) / 256, 256>>>(W_off, b_off, W_at, b_at);
    gemm_tf32<256><<<g256, blk>>>(value, W_val, b_val, vproj);
    gemm_tf32<NFUSE><<<g384, blk>>>(query, wf, bf, offattn);
    ms_sample_kernel<<<dim3(LQ, NB), blk>>>(refp);
    gemm_tf32<256><<<g256, blk>>>(accb, W_out, b_out, out);
}

// round 4
// speedup vs baseline: 2.2538x; 1.0247x over previous
#include <cuda_runtime.h>
#include <math.h>

// Problem constants (fixed by the reference)
#define NB 4
#define LQ 5440
#define LV 5440
#define CD 256
#define NH 8
#define HD 32
#define MROWS (NB * LQ)   // 21760
#define NFUSE 384         // fused off(256) + attn(128) projection width

// Scratch (device globals: no allocation allowed in kernel_launch)
__device__ float g_vproj  [(size_t)MROWS * CD];     // value @ W_val + b_val
__device__ float g_offattn[(size_t)MROWS * NFUSE];  // query @ [W_off|W_attn] + bias
__device__ float g_acc    [(size_t)MROWS * CD];     // sampled accumulator
__device__ float g_Wf     [256 * NFUSE];            // packed fused weights
__device__ float g_bf     [NFUSE];                  // packed fused bias

// ---------------------------------------------------------------------------
// Weight packing: Wf = [W_off | W_attn], bf = [b_off | b_attn]
// ---------------------------------------------------------------------------
__global__ void pack_weights(const float* __restrict__ W_off, const float* __restrict__ b_off,
                             const float* __restrict__ W_at,  const float* __restrict__ b_at)
{
    const int i = blockIdx.x * 256 + threadIdx.x;   // over 256*384
    const int k = i / NFUSE;
    const int n = i % NFUSE;
    g_Wf[i] = (n < 256) ? W_off[k * 256 + n] : W_at[k * 128 + (n - 256)];
    if (i < NFUSE) g_bf[i] = (i < 256) ? b_off[i] : b_at[i - 256];
}

// ---------------------------------------------------------------------------
// tf32 tensor-core GEMM: C[M, N] = A[M, 256] @ B[256, N] + bias[N]
// Block tile 128x128 (BK=16, double-buffered), 8 warps of 64x32.
// Operands converted to tf32 once at smem-store time.
// ---------------------------------------------------------------------------
__device__ __forceinline__ unsigned f2tf(float f) {
    unsigned r;
    asm("cvt.rna.tf32.f32 %0, %1;" : "=r"(r) : "f"(f));
    return r;
}

__device__ __forceinline__ void mma_tf32(float* c, const unsigned* a, const unsigned* b) {
    asm volatile(
        "mma.sync.aligned.m16n8k8.row.col.f32.tf32.tf32.f32 "
        "{%0,%1,%2,%3}, {%4,%5,%6,%7}, {%8,%9}, {%0,%1,%2,%3};"
        : "+f"(c[0]), "+f"(c[1]), "+f"(c[2]), "+f"(c[3])
        : "r"(a[0]), "r"(a[1]), "r"(a[2]), "r"(a[3]), "r"(b[0]), "r"(b[1]));
}

template <int N>
__global__ __launch_bounds__(256) void gemm_tf32(
    const float* __restrict__ A, const float* __restrict__ B,
    const float* __restrict__ bias, float* __restrict__ C)
{
    constexpr int K = 256;
    __shared__ __align__(16) unsigned As[2][128][20];   // [m][k] tf32 bits
    __shared__ __align__(16) unsigned Bs[2][16][136];   // [k][n] tf32 bits

    const int tid  = threadIdx.x;
    const int lane = tid & 31;
    const int warp = tid >> 5;
    const int br   = blockIdx.y;
    const int bc   = blockIdx.x;
    const int wm   = (warp >> 2) * 64;
    const int wn   = (warp & 3) * 32;

    const int arow0 = tid >> 2;            // 0..63 (+64)
    const int aq0   = (tid & 3) * 4;
    const int brow0 = tid >> 5;            // 0..7 (+8)
    const int bq0   = (tid & 31) * 4;

    const float* Abase = A + (size_t)(br * 128) * K;
    const float* Bbase = B + bc * 128;

    float4 la[2], lb[2];
    float acc[4][4][4] = {};

    auto stage_store = [&](int buf) {
#pragma unroll
        for (int i = 0; i < 2; i++) {
            unsigned* ap = &As[buf][arow0 + i * 64][aq0];
            ap[0] = f2tf(la[i].x); ap[1] = f2tf(la[i].y);
            ap[2] = f2tf(la[i].z); ap[3] = f2tf(la[i].w);
            unsigned* bp = &Bs[buf][brow0 + i * 8][bq0];
            bp[0] = f2tf(lb[i].x); bp[1] = f2tf(lb[i].y);
            bp[2] = f2tf(lb[i].z); bp[3] = f2tf(lb[i].w);
        }
    };

    // prologue
#pragma unroll
    for (int i = 0; i < 2; i++) {
        la[i] = *(const float4*)(Abase + (size_t)(arow0 + i * 64) * K + aq0);
        lb[i] = *(const float4*)(Bbase + (size_t)(brow0 + i * 8) * N + bq0);
    }
    stage_store(0);
    __syncthreads();

#pragma unroll 1
    for (int s = 0; s < K / 16; s++) {
        const int buf = s & 1;
        if (s + 1 < K / 16) {
            const int k0 = (s + 1) * 16;
#pragma unroll
            for (int i = 0; i < 2; i++) {
                la[i] = *(const float4*)(Abase + (size_t)(arow0 + i * 64) * K + k0 + aq0);
                lb[i] = *(const float4*)(Bbase + (size_t)(k0 + brow0 + i * 8) * N + bq0);
            }
        }

#pragma unroll
        for (int kk = 0; kk < 16; kk += 8) {
            unsigned af[4][4], bf[4][2];
            const int kc = kk + (lane & 3);
#pragma unroll
            for (int mi = 0; mi < 4; mi++) {
                const int row = wm + mi * 16 + (lane >> 2);
                af[mi][0] = As[buf][row][kc];
                af[mi][1] = As[buf][row + 8][kc];
                af[mi][2] = As[buf][row][kc + 4];
                af[mi][3] = As[buf][row + 8][kc + 4];
            }
#pragma unroll
            for (int ni = 0; ni < 4; ni++) {
                const int col = wn + ni * 8 + (lane >> 2);
                bf[ni][0] = Bs[buf][kc][col];
                bf[ni][1] = Bs[buf][kc + 4][col];
            }
#pragma unroll
            for (int mi = 0; mi < 4; mi++)
#pragma unroll
                for (int ni = 0; ni < 4; ni++)
                    mma_tf32(acc[mi][ni], af[mi], bf[ni]);
        }

        if (s + 1 < K / 16) {
            stage_store((s + 1) & 1);
            __syncthreads();
        }
    }

    // epilogue
#pragma unroll
    for (int mi = 0; mi < 4; mi++) {
        const int r = br * 128 + wm + mi * 16 + (lane >> 2);
#pragma unroll
        for (int ni = 0; ni < 4; ni++) {
            const int c = bc * 128 + wn + ni * 8 + (lane & 3) * 2;
            const float2 bv = *(const float2*)&bias[c];
            float2 o0, o1;
            o0.x = acc[mi][ni][0] + bv.x;
            o0.y = acc[mi][ni][1] + bv.y;
            o1.x = acc[mi][ni][2] + bv.x;
            o1.y = acc[mi][ni][3] + bv.y;
            *(float2*)&C[(size_t)r * N + c]       = o0;
            *(float2*)&C[(size_t)(r + 8) * N + c] = o1;
        }
    }
}

// ---------------------------------------------------------------------------
// Deformable sampling — warp-autonomous version (NO block barriers).
// Warp = (q, h). Lanes 0-15: fused softmax + tap build -> 512B per-warp smem.
// One __syncwarp(), then all 32 lanes gather (8 lanes/tap, LDG.128 = 4 taps
// per instruction, branchless), xor-shuffle reduce, lanes 0-7 store float4.
// ---------------------------------------------------------------------------
__global__ __launch_bounds__(256) void ms_sample_kernel(
    const float* __restrict__ refp)   // [B, Lq, 4, 2]
{
    const int q  = blockIdx.x;
    const int b  = blockIdx.y;
    const int bq = b * LQ + q;
    const int t  = threadIdx.x;
    const int h  = t >> 5;
    const int lid = t & 31;

    __shared__ int2 s_tap[NH][64];   // {value-row idx, weight bits} per warp

    // --- fused softmax + tap precompute (lanes 0-15, lp = lane)
    {
        const int lp = lid;
        const float* ap = g_offattn + (size_t)bq * NFUSE + 256 + h * 16;
        float logit = (lid < 16) ? ap[lp] : -1e30f;
        // reduce within the 16-lane half (offsets 1..8)
        float m = logit;
#pragma unroll
        for (int o = 8; o; o >>= 1) m = fmaxf(m, __shfl_xor_sync(0xFFFFFFFFu, m, o));
        float e = (lid < 16) ? __expf(logit - m) : 0.0f;
        float ssum = e;
#pragma unroll
        for (int o = 8; o; o >>= 1) ssum += __shfl_xor_sync(0xFFFFFFFFu, ssum, o);

        if (lid < 16) {
            const float aw = e / ssum;
            const int l = lp >> 2;
            const int W = 64 >> l;
            const int start = (l == 0) ? 0 : (l == 1) ? 4096 : (l == 2) ? 5120 : 5376;

            const float rx = refp[((size_t)bq * 4 + l) * 2 + 0];
            const float ry = refp[((size_t)bq * 4 + l) * 2 + 1];
            const float* op = g_offattn + (size_t)bq * NFUSE + h * 32 + lp * 2;

            const float x = fmaf(rx, (float)W, op[0]) - 0.5f;
            const float y = fmaf(ry, (float)W, op[1]) - 0.5f;
            const float x0f = floorf(x), y0f = floorf(y);
            const int x0 = (int)x0f, y0 = (int)y0f;
            const float wx = x - x0f, wy = y - y0f;

            const bool xi0 = (x0 >= 0) && (x0 < W);
            const bool xi1 = (x0 + 1 >= 0) && (x0 + 1 < W);
            const bool yi0 = (y0 >= 0) && (y0 < W);
            const bool yi1 = (y0 + 1 >= 0) && (y0 + 1 < W);

            const int i00 = start + y0 * W + x0;
            int2* tp = &s_tap[h][lp * 4];
            bool v;
            v = xi0 && yi0;
            tp[0] = make_int2(v ? i00 : 0,         __float_as_int(v ? aw * (1.f - wx) * (1.f - wy) : 0.f));
            v = xi1 && yi0;
            tp[1] = make_int2(v ? i00 + 1 : 0,     __float_as_int(v ? aw * wx * (1.f - wy) : 0.f));
            v = xi0 && yi1;
            tp[2] = make_int2(v ? i00 + W : 0,     __float_as_int(v ? aw * (1.f - wx) * wy : 0.f));
            v = xi1 && yi1;
            tp[3] = make_int2(v ? i00 + W + 1 : 0, __float_as_int(v ? aw * wx * wy : 0.f));
        }
    }
    __syncwarp();

    // --- gather: 8 lanes per tap, float4 channels per lane, branchless
    const int sub = lid >> 3;         // tap sub-slot 0..3
    const int c4  = (lid & 7) * 4;    // channel quad
    const float* vb4 = g_vproj + (size_t)b * LV * CD + h * HD + c4;
    const int2* taps = &s_tap[h][0];

    float ax = 0.f, ay = 0.f, az = 0.f, aw_ = 0.f;
#pragma unroll
    for (int j = 0; j < 16; j++) {
        const int2 tv = taps[j * 4 + sub];
        const float w = __int_as_float(tv.y);
        const float4 v = *(const float4*)(vb4 + (size_t)tv.x * CD);
        ax  = fmaf(w, v.x, ax);
        ay  = fmaf(w, v.y, ay);
        az  = fmaf(w, v.z, az);
        aw_ = fmaf(w, v.w, aw_);
    }

    // reduce the 4 tap sub-slots (lanes l, l^8, l^16, l^24)
#pragma unroll
    for (int o = 8; o <= 16; o <<= 1) {
        ax  += __shfl_xor_sync(0xFFFFFFFFu, ax,  o);
        ay  += __shfl_xor_sync(0xFFFFFFFFu, ay,  o);
        az  += __shfl_xor_sync(0xFFFFFFFFu, az,  o);
        aw_ += __shfl_xor_sync(0xFFFFFFFFu, aw_, o);
    }

    if (lid < 8) {
        float4 o4 = make_float4(ax, ay, az, aw_);
        *(float4*)&g_acc[(size_t)bq * CD + h * HD + lid * 4] = o4;
    }
}

// ---------------------------------------------------------------------------
// kernel_launch
// Inputs: query, reference_points, value, W_off, b_off, W_attn, b_attn,
//         W_val, b_val, W_out, b_out
// ---------------------------------------------------------------------------
extern "C" void kernel_launch(void* const* d_in, const int* in_sizes, int n_in,
                              void* d_out, int out_size)
{
    const float* query = (const float*)d_in[0];
    const float* refp  = (const float*)d_in[1];
    const float* value = (const float*)d_in[2];
    const float* W_off = (const float*)d_in[3];
    const float* b_off = (const float*)d_in[4];
    const float* W_at  = (const float*)d_in[5];
    const float* b_at  = (const float*)d_in[6];
    const float* W_val = (const float*)d_in[7];
    const float* b_val = (const float*)d_in[8];
    const float* W_out = (const float*)d_in[9];
    const float* b_out = (const float*)d_in[10];
    float* out = (float*)d_out;

    float *vproj, *offattn, *accb, *wf, *bf;
    cudaGetSymbolAddress((void**)&vproj,   g_vproj);
    cudaGetSymbolAddress((void**)&offattn, g_offattn);
    cudaGetSymbolAddress((void**)&accb,    g_acc);
    cudaGetSymbolAddress((void**)&wf,      g_Wf);
    cudaGetSymbolAddress((void**)&bf,      g_bf);

    dim3 blk(256);
    dim3 g256(CD / 128, MROWS / 128);     // (2, 170)
    dim3 g384(NFUSE / 128, MROWS / 128);  // (3, 170)

    pack_weights<<<(256 * NFUSE) / 256, 256>>>(W_off, b_off, W_at, b_at);
    gemm_tf32<256><<<g256, blk>>>(value, W_val, b_val, vproj);
    gemm_tf32<NFUSE><<<g384, blk>>>(query, wf, bf, offattn);
    ms_sample_kernel<<<dim3(LQ, NB), blk>>>(refp);
    gemm_tf32<256><<<g256, blk>>>(accb, W_out, b_out, out);
}